// round 17
// baseline (speedup 1.0000x reference)
#include <cuda_runtime.h>
#include <mma.h>
using namespace nvcuda;

#define NPT 16384
#define BB  2

__device__ float g_f [BB*NPT*64];
__device__ float g_q [BB*NPT*64];     // QS = s0*q - t0
__device__ float g_kv[BB*NPT*128];    // [row][0:64]=s0*(k+pr), [64:128]=v+pr
__device__ float g_xm[BB*NPT*64];

__device__ float g_W1f[32*64];
__device__ float g_t1[64];
__device__ float g_WqT[64*64], g_WkT[64*64], g_WvT[64*64];
__device__ float g_bqv[64], g_bkv[64], g_bvv[64];
__device__ float g_Wp1f[9], g_tp[3];
__device__ float g_Wp2b[64*4];
__device__ float g_s0t0[64*2];
__device__ float g_Ww1f[64*8];
__device__ float g_tw1[8], g_Ww2m[64], g_bw2v[8];
__device__ float g_smt[64*2];
__device__ float g_W2T[64*64], g_t2[64];

__device__ __forceinline__ float lrelu(float x) { return fmaxf(x, 0.2f*x); }

// ---------------- prep: 64 blocks x 64 threads ------------------------------
__global__ void k_prep(const float* __restrict__ W1,  const float* __restrict__ bn1,
                       const float* __restrict__ Wq,  const float* __restrict__ bq,
                       const float* __restrict__ Wk,  const float* __restrict__ bk,
                       const float* __restrict__ Wv,  const float* __restrict__ bv,
                       const float* __restrict__ Wp1, const float* __restrict__ bnp1,
                       const float* __restrict__ Wp2, const float* __restrict__ bp2,
                       const float* __restrict__ bnw0,const float* __restrict__ Ww1,
                       const float* __restrict__ bnw1,const float* __restrict__ Ww2,
                       const float* __restrict__ bw2, const float* __restrict__ bn_mid,
                       const float* __restrict__ W2,  const float* __restrict__ bn2)
{
    int c = blockIdx.x;
    int i = threadIdx.x;
    float s1 = bn1[c] * rsqrtf(bn1[192+c] + 1e-5f);
    float s2 = bn2[c] * rsqrtf(bn2[192+c] + 1e-5f);
    if (i < 32) g_W1f[i*64+c] = W1[c*32+i]*s1;
    g_WqT[i*64+c] = Wq[c*64+i];
    g_WkT[i*64+c] = Wk[c*64+i];
    g_WvT[i*64+c] = Wv[c*64+i];
    g_W2T[i*64+c] = W2[c*64+i]*s2;
    if (i < 8) {
        float sw = bnw1[i] * rsqrtf(bnw1[24+i] + 1e-5f);
        g_Ww1f[c*8+i] = Ww1[i*64+c]*sw;
    }
    if (i == 0) {
        g_t1[c] = bn1[64+c] - bn1[128+c]*s1;
        g_bqv[c] = bq[c]; g_bkv[c] = bk[c]; g_bvv[c] = bv[c];
        g_Wp2b[c*4+0] = Wp2[c*3+0];
        g_Wp2b[c*4+1] = Wp2[c*3+1];
        g_Wp2b[c*4+2] = Wp2[c*3+2];
        g_Wp2b[c*4+3] = bp2[c];
        float s0 = bnw0[c] * rsqrtf(bnw0[192+c] + 1e-5f);
        g_s0t0[c*2+0] = s0;
        g_s0t0[c*2+1] = bnw0[64+c] - bnw0[128+c]*s0;
        float sm = bn_mid[c] * rsqrtf(bn_mid[192+c] + 1e-5f);
        g_smt[c*2+0] = sm;
        g_smt[c*2+1] = bn_mid[64+c] - bn_mid[128+c]*sm;
        g_t2[c] = bn2[64+c] - bn2[128+c]*s2;
    }
    if (c == 0) {
        if (i < 3) {
            float sp = bnp1[i] * rsqrtf(bnp1[9+i] + 1e-5f);
            g_Wp1f[i*3+0] = Wp1[i*3+0]*sp;
            g_Wp1f[i*3+1] = Wp1[i*3+1]*sp;
            g_Wp1f[i*3+2] = Wp1[i*3+2]*sp;
            g_tp[i] = bnp1[3+i] - bnp1[6+i]*sp;
        }
        if (i < 8) {
            float sw = bnw1[i] * rsqrtf(bnw1[24+i] + 1e-5f);
            g_tw1[i]  = bnw1[8+i] - bnw1[16+i]*sw;
            g_bw2v[i] = bw2[i];
        }
        g_Ww2m[i] = Ww2[i];
    }
}

// ---------------- fused projections: f fp32 SIMT; q/k/v tf32 wmma -----------
__global__ void __launch_bounds__(256) k_proj(const float* __restrict__ feat,
                                              const float* __restrict__ xyz)
{
    __shared__ __align__(128) float sfe[32*68];
    __shared__ __align__(128) float sfA[64*72];  // f, [p][c], ldm 72
    __shared__ __align__(128) float sC [64*72];  // GEMM out, [p][c], ldm 72
    __shared__ float sh [64*4];
    int t  = threadIdx.x;
    int b  = blockIdx.y;
    int n0 = blockIdx.x * 64;
    size_t base = (size_t)b*NPT + n0;

    #pragma unroll
    for (int r = 0; r < 8; r++) {
        int li = r*256 + t;
        int i = li >> 6, p = li & 63;
        sfe[i*68+p] = feat[(size_t)(b*32 + i)*NPT + n0 + p];
    }
    if (t < 64) {
        const float* xr = xyz + (base + t)*3;
        float X = xr[0], Y = xr[1], Z = xr[2];
        sh[t*4+0] = fmaxf(fmaf(g_Wp1f[0], X, fmaf(g_Wp1f[1], Y, fmaf(g_Wp1f[2], Z, g_tp[0]))), 0.f);
        sh[t*4+1] = fmaxf(fmaf(g_Wp1f[3], X, fmaf(g_Wp1f[4], Y, fmaf(g_Wp1f[5], Z, g_tp[1]))), 0.f);
        sh[t*4+2] = fmaxf(fmaf(g_Wp1f[6], X, fmaf(g_Wp1f[7], Y, fmaf(g_Wp1f[8], Z, g_tp[2]))), 0.f);
    }
    __syncthreads();

    int cc = t & 15, pg = t >> 4;
    int cb = 4*cc, pb = 4*pg;

    // ---- f = relu(W1f x + t1), fp32 SIMT; store point-major
    {
        float af[4][4];
        #pragma unroll
        for (int x = 0; x < 4; x++)
            #pragma unroll
            for (int y = 0; y < 4; y++) af[x][y] = 0.f;

        #pragma unroll
        for (int i = 0; i < 32; i++) {
            float4 w  = *(const float4*)&g_W1f[i*64 + cb];
            float4 fv = *(const float4*)&sfe[i*68 + pb];
            float wc[4] = {w.x,w.y,w.z,w.w};
            float fp[4] = {fv.x,fv.y,fv.z,fv.w};
            #pragma unroll
            for (int ch = 0; ch < 4; ch++)
                #pragma unroll
                for (int pp = 0; pp < 4; pp++)
                    af[ch][pp] = fmaf(wc[ch], fp[pp], af[ch][pp]);
        }
        float4 t1v = *(const float4*)&g_t1[cb];
        float tb[4] = {t1v.x, t1v.y, t1v.z, t1v.w};
        #pragma unroll
        for (int ch = 0; ch < 4; ch++)
            #pragma unroll
            for (int pp = 0; pp < 4; pp++)
                af[ch][pp] = fmaxf(af[ch][pp] + tb[ch], 0.f);
        #pragma unroll
        for (int pp = 0; pp < 4; pp++) {
            float4 v = make_float4(af[0][pp], af[1][pp], af[2][pp], af[3][pp]);
            *(float4*)&sfA[(pb+pp)*72 + cb] = v;
            *(float4*)&g_f[(base + pb + pp)*64 + cb] = v;
        }
    }
    __syncthreads();

    int warp = t >> 5;

    // ---- projections with tf32 wmma: z=0 QS, z=1 K', z=2 V'
    for (int z = 0; z < 3; z++) {
        const float* W    = (z == 0) ? g_WqT : (z == 1) ? g_WkT : g_WvT;
        const float* bias = (z == 0) ? g_bqv : (z == 1) ? g_bkv : g_bvv;

        #pragma unroll
        for (int tt = 0; tt < 2; tt++) {
            int tile = warp*2 + tt, mi = tile >> 2, ni = tile & 3;
            wmma::fragment<wmma::accumulator, 16, 16, 8, float> cfr;
            wmma::fill_fragment(cfr, 0.f);
            #pragma unroll
            for (int k0 = 0; k0 < 8; k0++) {
                wmma::fragment<wmma::matrix_a, 16, 16, 8, wmma::precision::tf32, wmma::row_major> afr;
                wmma::fragment<wmma::matrix_b, 16, 16, 8, wmma::precision::tf32, wmma::row_major> bfr;
                wmma::load_matrix_sync(afr, &sfA[mi*16*72 + k0*8], 72);
                wmma::load_matrix_sync(bfr, &W[k0*8*64 + ni*16], 64);
                #pragma unroll
                for (int x = 0; x < afr.num_elements; x++) afr.x[x] = wmma::__float_to_tf32(afr.x[x]);
                #pragma unroll
                for (int x = 0; x < bfr.num_elements; x++) bfr.x[x] = wmma::__float_to_tf32(bfr.x[x]);
                wmma::mma_sync(cfr, afr, bfr, cfr);
            }
            wmma::store_matrix_sync(&sC[mi*16*72 + ni*16], cfr, 72, wmma::mem_row_major);
        }
        __syncthreads();

        float4 bb = *(const float4*)&bias[cb];
        float bvr[4] = {bb.x, bb.y, bb.z, bb.w};

        if (z == 0) {
            #pragma unroll
            for (int pp = 0; pp < 4; pp++) {
                float4 av = *(const float4*)&sC[(pb+pp)*72 + cb];
                float ar[4] = {av.x, av.y, av.z, av.w};
                float o[4];
                #pragma unroll
                for (int ch = 0; ch < 4; ch++) {
                    float2 st = *(const float2*)&g_s0t0[(cb+ch)*2];
                    o[ch] = fmaf(st.x, ar[ch] + bvr[ch], -st.y);
                }
                *(float4*)&g_q[(base + pb + pp)*64 + cb] =
                    make_float4(o[0], o[1], o[2], o[3]);
            }
        } else {
            float* dst = (z == 1) ? g_kv : (g_kv + 64);
            #pragma unroll
            for (int pp = 0; pp < 4; pp++) {
                float4 av = *(const float4*)&sC[(pb+pp)*72 + cb];
                float ar[4] = {av.x, av.y, av.z, av.w};
                float h0 = sh[(pb+pp)*4+0], h1 = sh[(pb+pp)*4+1], h2 = sh[(pb+pp)*4+2];
                float o[4];
                #pragma unroll
                for (int ch = 0; ch < 4; ch++) {
                    float4 wp = *(const float4*)&g_Wp2b[(cb+ch)*4];
                    float pr = fmaf(wp.x, h0, fmaf(wp.y, h1, fmaf(wp.z, h2, wp.w)));
                    float val = ar[ch] + bvr[ch] + pr;
                    if (z == 1) val *= g_s0t0[(cb+ch)*2];
                    o[ch] = val;
                }
                *(float4*)&dst[(base + pb + pp)*128 + cb] =
                    make_float4(o[0], o[1], o[2], o[3]);
            }
        }
        __syncthreads();
    }
}

// ---------------- attention core: 2 points per warp (R15 winner) ------------
#define WPB 4
__global__ void __launch_bounds__(128) k_attn(const int* __restrict__ nidx)
{
    __shared__ float skv[WPB][2][16*64];
    __shared__ float swt[WPB][2][132];
    __shared__ float sWw1f[512];
    __shared__ float sWw2[64];
    __shared__ float sAux[16];

    int t = threadIdx.x;
    sWw1f[t]       = g_Ww1f[t];
    sWw1f[128+t]   = g_Ww1f[128+t];
    sWw1f[256+t]   = g_Ww1f[256+t];
    sWw1f[384+t]   = g_Ww1f[384+t];
    if (t < 64)    sWw2[t] = g_Ww2m[t];
    if (t < 8)   { sAux[t] = g_tw1[t]; sAux[8+t] = g_bw2v[t]; }
    __syncthreads();

    int warp = t >> 5, l = t & 31;
    int pidA = blockIdx.x * (WPB*2) + warp*2;
    int b    = pidA >> 14;
    size_t rowb   = (size_t)b * NPT;
    size_t pbaseA = (rowb + (pidA & 16383)) * 64;
    size_t pbaseB = pbaseA + 64;

    int k = l & 15, h = l >> 4;
    int c0 = 32 * h;

    int myidx = __ldg(nidx + (size_t)pidA*16 + l);

    float* skvA = skv[warp][0];
    float* skvB = skv[warp][1];
    int i2 = l >> 4, ch16 = l & 15;
    #pragma unroll
    for (int i = 0; i < 8; i++) {
        int row = 2*i + i2;
        int rA = __shfl_sync(0xffffffffu, myidx, row);
        int rB = __shfl_sync(0xffffffffu, myidx, 16 + row);
        int pp = ch16 ^ (row & 7);
        {
            const float4* src = (const float4*)(g_kv + (rowb + rA)*128) + ch16;
            unsigned dst = (unsigned)__cvta_generic_to_shared(&skvA[row*64 + pp*4]);
            asm volatile("cp.async.cg.shared.global [%0], [%1], 16;" :: "r"(dst), "l"(src));
        }
        {
            const float4* src = (const float4*)(g_kv + (rowb + rB)*128) + ch16;
            unsigned dst = (unsigned)__cvta_generic_to_shared(&skvB[row*64 + pp*4]);
            asm volatile("cp.async.cg.shared.global [%0], [%1], 16;" :: "r"(dst), "l"(src));
        }
    }
    asm volatile("cp.async.commit_group;" ::: "memory");
    asm volatile("cp.async.wait_group 0;" ::: "memory");
    __syncwarp();

    float w1A[8], w1B[8];
    #pragma unroll
    for (int j = 0; j < 8; j++) { w1A[j] = 0.f; w1B[j] = 0.f; }

    int sw8 = k & 7;
    #pragma unroll
    for (int s = 0; s < 8; s++) {
        int c = c0 + 4*s;
        int co = ((h*8 + s) ^ sw8)*4;
        float4 kkA = *(const float4*)&skvA[k*64 + co];
        float4 kkB = *(const float4*)&skvB[k*64 + co];
        float4 qsA = __ldg((const float4*)(g_q + pbaseA + c));
        float4 qsB = __ldg((const float4*)(g_q + pbaseB + c));
        float uA[4] = { lrelu(kkA.x-qsA.x), lrelu(kkA.y-qsA.y),
                        lrelu(kkA.z-qsA.z), lrelu(kkA.w-qsA.w) };
        float uB[4] = { lrelu(kkB.x-qsB.x), lrelu(kkB.y-qsB.y),
                        lrelu(kkB.z-qsB.z), lrelu(kkB.w-qsB.w) };
        #pragma unroll
        for (int e = 0; e < 4; e++) {
            int ch = c + e;
            float4 wA = *(const float4*)(sWw1f + ch*8);
            float4 wB = *(const float4*)(sWw1f + ch*8 + 4);
            float ua = uA[e], ub = uB[e];
            w1A[0] = fmaf(wA.x, ua, w1A[0]); w1A[1] = fmaf(wA.y, ua, w1A[1]);
            w1A[2] = fmaf(wA.z, ua, w1A[2]); w1A[3] = fmaf(wA.w, ua, w1A[3]);
            w1A[4] = fmaf(wB.x, ua, w1A[4]); w1A[5] = fmaf(wB.y, ua, w1A[5]);
            w1A[6] = fmaf(wB.z, ua, w1A[6]); w1A[7] = fmaf(wB.w, ua, w1A[7]);
            w1B[0] = fmaf(wA.x, ub, w1B[0]); w1B[1] = fmaf(wA.y, ub, w1B[1]);
            w1B[2] = fmaf(wA.z, ub, w1B[2]); w1B[3] = fmaf(wA.w, ub, w1B[3]);
            w1B[4] = fmaf(wB.x, ub, w1B[4]); w1B[5] = fmaf(wB.y, ub, w1B[5]);
            w1B[6] = fmaf(wB.z, ub, w1B[6]); w1B[7] = fmaf(wB.w, ub, w1B[7]);
        }
    }

    #pragma unroll
    for (int j = 0; j < 8; j++) {
        w1A[j] += __shfl_xor_sync(0xffffffffu, w1A[j], 16);
        w1B[j] += __shfl_xor_sync(0xffffffffu, w1B[j], 16);
    }

    float4 tA4 = *(const float4*)&sAux[0];
    float4 tB4 = *(const float4*)&sAux[4];
    float tw[8] = {tA4.x,tA4.y,tA4.z,tA4.w,tB4.x,tB4.y,tB4.z,tB4.w};
    float2 bwl = *(const float2*)&sAux[8 + 4*h + 0];
    float2 bwh = *(const float2*)&sAux[8 + 4*h + 2];
    float bwr[4] = {bwl.x, bwl.y, bwh.x, bwh.y};

    {
        float w1v[8];
        #pragma unroll
        for (int j = 0; j < 8; j++) w1v[j] = fmaxf(w1A[j] + tw[j], 0.f);
        float wt[4];
        #pragma unroll
        for (int jj = 0; jj < 4; jj++) {
            int j = 4*h + jj;
            float4 rA = *(const float4*)&sWw2[j*8];
            float4 rB = *(const float4*)&sWw2[j*8 + 4];
            float a = bwr[jj];
            a = fmaf(rA.x, w1v[0], a); a = fmaf(rA.y, w1v[1], a);
            a = fmaf(rA.z, w1v[2], a); a = fmaf(rA.w, w1v[3], a);
            a = fmaf(rB.x, w1v[4], a); a = fmaf(rB.y, w1v[5], a);
            a = fmaf(rB.z, w1v[6], a); a = fmaf(rB.w, w1v[7], a);
            wt[jj] = a;
        }
        *(float4*)&swt[warp][0][k*8 + 4*h] = make_float4(wt[0], wt[1], wt[2], wt[3]);
    }
    {
        float w1v[8];
        #pragma unroll
        for (int j = 0; j < 8; j++) w1v[j] = fmaxf(w1B[j] + tw[j], 0.f);
        float wt[4];
        #pragma unroll
        for (int jj = 0; jj < 4; jj++) {
            int j = 4*h + jj;
            float4 rA = *(const float4*)&sWw2[j*8];
            float4 rB = *(const float4*)&sWw2[j*8 + 4];
            float a = bwr[jj];
            a = fmaf(rA.x, w1v[0], a); a = fmaf(rA.y, w1v[1], a);
            a = fmaf(rA.z, w1v[2], a); a = fmaf(rA.w, w1v[3], a);
            a = fmaf(rB.x, w1v[4], a); a = fmaf(rB.y, w1v[5], a);
            a = fmaf(rB.z, w1v[6], a); a = fmaf(rB.w, w1v[7], a);
            wt[jj] = a;
        }
        *(float4*)&swt[warp][1][k*8 + 4*h] = make_float4(wt[0], wt[1], wt[2], wt[3]);
    }
    __syncwarp();

    #pragma unroll
    for (int pt = 0; pt < 2; pt++) {
        float* swp = swt[warp][pt];
        int j = l >> 2, kq = l & 3;
        float v0 = swp[(4*kq+0)*8 + j];
        float v1 = swp[(4*kq+1)*8 + j];
        float v2 = swp[(4*kq+2)*8 + j];
        float v3 = swp[(4*kq+3)*8 + j];
        float mx = fmaxf(fmaxf(v0, v1), fmaxf(v2, v3));
        mx = fmaxf(mx, __shfl_xor_sync(0xffffffffu, mx, 1));
        mx = fmaxf(mx, __shfl_xor_sync(0xffffffffu, mx, 2));
        float e0 = __expf(v0 - mx), e1 = __expf(v1 - mx);
        float e2 = __expf(v2 - mx), e3 = __expf(v3 - mx);
        float sm = e0 + e1 + e2 + e3;
        sm += __shfl_xor_sync(0xffffffffu, sm, 1);
        sm += __shfl_xor_sync(0xffffffffu, sm, 2);
        float inv = __fdividef(1.f, sm);
        swp[(4*kq+0)*8 + j] = e0 * inv;
        swp[(4*kq+1)*8 + j] = e1 * inv;
        swp[(4*kq+2)*8 + j] = e2 * inv;
        swp[(4*kq+3)*8 + j] = e3 * inv;
    }
    __syncwarp();

    int cc0 = 2*l;
    int j0 = cc0 & 7;
    float a0 = 0.f, a1 = 0.f, b0 = 0.f, b1 = 0.f;
    #pragma unroll
    for (int kk2 = 0; kk2 < 16; kk2++) {
        float2 wvA = *(const float2*)&swt[warp][0][kk2*8 + j0];
        float2 wvB = *(const float2*)&swt[warp][1][kk2*8 + j0];
        int rA = __shfl_sync(0xffffffffu, myidx, kk2);
        int rB = __shfl_sync(0xffffffffu, myidx, 16 + kk2);
        float2 vA = __ldg((const float2*)(g_kv + (rowb + rA)*128 + 64 + cc0));
        float2 vB = __ldg((const float2*)(g_kv + (rowb + rB)*128 + 64 + cc0));
        a0 = fmaf(wvA.x, vA.x, a0); a1 = fmaf(wvA.y, vA.y, a1);
        b0 = fmaf(wvB.x, vB.x, b0); b1 = fmaf(wvB.y, vB.y, b1);
    }

    float4 sm4 = *(const float4*)(g_smt + 4*l);
    float xa0 = lrelu(fmaf(sm4.x, a0, sm4.y));
    float xa1 = lrelu(fmaf(sm4.z, a1, sm4.w));
    float xb0 = lrelu(fmaf(sm4.x, b0, sm4.y));
    float xb1 = lrelu(fmaf(sm4.z, b1, sm4.w));
    *(float2*)&g_xm[pbaseA + cc0] = make_float2(xa0, xa1);
    *(float2*)&g_xm[pbaseB + cc0] = make_float2(xb0, xb1);
}

// ---------------- conv2 via tf32 wmma + residual + lrelu --------------------
__global__ void __launch_bounds__(256) k_out(float* __restrict__ out)
{
    __shared__ __align__(128) float sC[64*72];   // [p][c]
    __shared__ float sT[64*68];                  // [c][p]
    int t  = threadIdx.x;
    int b  = blockIdx.y;
    int n0 = blockIdx.x * 64;
    size_t base = (size_t)b*NPT + n0;

    int warp = t >> 5;
    #pragma unroll
    for (int tt = 0; tt < 2; tt++) {
        int tile = warp*2 + tt, mi = tile >> 2, ni = tile & 3;
        wmma::fragment<wmma::accumulator, 16, 16, 8, float> cfr;
        wmma::fill_fragment(cfr, 0.f);
        #pragma unroll
        for (int k0 = 0; k0 < 8; k0++) {
            wmma::fragment<wmma::matrix_a, 16, 16, 8, wmma::precision::tf32, wmma::row_major> afr;
            wmma::fragment<wmma::matrix_b, 16, 16, 8, wmma::precision::tf32, wmma::row_major> bfr;
            wmma::load_matrix_sync(afr, &g_xm[(base + mi*16)*64 + k0*8], 64);
            wmma::load_matrix_sync(bfr, &g_W2T[k0*8*64 + ni*16], 64);
            #pragma unroll
            for (int x = 0; x < afr.num_elements; x++) afr.x[x] = wmma::__float_to_tf32(afr.x[x]);
            #pragma unroll
            for (int x = 0; x < bfr.num_elements; x++) bfr.x[x] = wmma::__float_to_tf32(bfr.x[x]);
            wmma::mma_sync(cfr, afr, bfr, cfr);
        }
        wmma::store_matrix_sync(&sC[mi*16*72 + ni*16], cfr, 72, wmma::mem_row_major);
    }
    __syncthreads();

    int cc = t & 15, pg = t >> 4;
    int cb = 4*cc, pb = 4*pg;

    float4 t2v = *(const float4*)&g_t2[cb];
    float tb[4] = {t2v.x, t2v.y, t2v.z, t2v.w};
    #pragma unroll
    for (int pp = 0; pp < 4; pp++) {
        float4 av = *(const float4*)&sC[(pb+pp)*72 + cb];
        float ar[4] = {av.x, av.y, av.z, av.w};
        float4 fv = *(const float4*)&g_f[(base + pb + pp)*64 + cb];
        float fr[4] = {fv.x, fv.y, fv.z, fv.w};
        #pragma unroll
        for (int ch = 0; ch < 4; ch++)
            sT[(cb+ch)*68 + pb + pp] = lrelu(ar[ch] + tb[ch] + fr[ch]);
    }
    __syncthreads();

    int cO = t >> 2, q = t & 3;
    #pragma unroll
    for (int i = 0; i < 4; i++) {
        float4 vq = *(const float4*)&sT[cO*68 + q*16 + 4*i];
        *(float4*)&out[((size_t)(b*64 + cO))*NPT + n0 + q*16 + 4*i] = vq;
    }
}

extern "C" void kernel_launch(void* const* d_in, const int* in_sizes, int n_in,
                              void* d_out, int out_size)
{
    const float* feature = (const float*)d_in[0];
    const float* xyz     = (const float*)d_in[1];
    const float* W1      = (const float*)d_in[2];
    const float* bn1     = (const float*)d_in[3];
    const float* Wq      = (const float*)d_in[4];
    const float* bq      = (const float*)d_in[5];
    const float* Wk      = (const float*)d_in[6];
    const float* bk      = (const float*)d_in[7];
    const float* Wv      = (const float*)d_in[8];
    const float* bv      = (const float*)d_in[9];
    const float* Wp1     = (const float*)d_in[10];
    const float* bnp1    = (const float*)d_in[11];
    const float* Wp2     = (const float*)d_in[12];
    const float* bp2     = (const float*)d_in[13];
    const float* bnw0    = (const float*)d_in[14];
    const float* Ww1     = (const float*)d_in[15];
    const float* bnw1    = (const float*)d_in[16];
    const float* Ww2     = (const float*)d_in[17];
    const float* bw2     = (const float*)d_in[18];
    const float* bn_mid  = (const float*)d_in[19];
    const float* W2      = (const float*)d_in[20];
    const float* bn2     = (const float*)d_in[21];
    const int*   nidx    = (const int*)d_in[22];
    float* out = (float*)d_out;

    k_prep<<<64, 64>>>(W1, bn1, Wq, bq, Wk, bk, Wv, bv, Wp1, bnp1, Wp2, bp2,
                       bnw0, Ww1, bnw1, Ww2, bw2, bn_mid, W2, bn2);
    dim3 gf(NPT/64, BB);
    k_proj<<<gf, 256>>>(feature, xyz);
    k_attn<<<(BB*NPT)/(WPB*2), 128>>>(nidx);
    k_out<<<gf, 256>>>(out);
}